// round 14
// baseline (speedup 1.0000x reference)
#include <cuda_runtime.h>
#include <cuda_bf16.h>
#include <math.h>
#include <stdint.h>

#define N_ROWS 8192
#define DIM    512
#define KSUB   160          // screening subspace (first 160 dims)
#define TWO_N  16384

// ================= device scratch =================
__device__ float g_mean[2][DIM];
__device__ float g_energy[2][DIM];
__device__ float g_var[2][DIM];
__device__ float g_kurt[2][DIM];
__device__ float g_skew[2][DIM];
__device__ float g_rnsub[TWO_N];             // squared norm over first KSUB dims
__device__ float g_cacc[2][4][DIM];          // raw moment partials S1..S4
__device__ float g_acc[4];                   // 0 mmd-sum, 1 log(p) src, 2 log(1-p) tgt, 3 weight
__device__ __nv_bfloat16 g_ubf[(size_t)TWO_N * DIM];   // bf16 copy of u=[s;t], full 512 dims
__device__ __nv_bfloat16 g_w1t[256 * 512];   // W1^T bf16 [n][k]
__device__ __nv_bfloat16 g_w2t[128 * 256];   // W2^T bf16 [n][k]

// ================= helpers =================
__device__ __forceinline__ void cp16(uint32_t dst_smem, const void* src) {
    asm volatile("cp.async.cg.shared.global [%0], [%1], 16;" :: "r"(dst_smem), "l"(src));
}
__device__ __forceinline__ void mma16816(float* c, const uint32_t* a, const uint32_t* b) {
    asm volatile(
        "mma.sync.aligned.m16n8k16.row.col.f32.bf16.bf16.f32 "
        "{%0,%1,%2,%3}, {%4,%5,%6,%7}, {%8,%9}, {%0,%1,%2,%3};"
        : "+f"(c[0]), "+f"(c[1]), "+f"(c[2]), "+f"(c[3])
        : "r"(a[0]), "r"(a[1]), "r"(a[2]), "r"(a[3]), "r"(b[0]), "r"(b[1]));
}
__device__ __forceinline__ void ldm_x4(uint32_t* r, uint32_t addr) {
    asm volatile("ldmatrix.sync.aligned.m8n8.x4.shared.b16 {%0,%1,%2,%3}, [%4];"
        : "=r"(r[0]), "=r"(r[1]), "=r"(r[2]), "=r"(r[3]) : "r"(addr));
}

// ================= init: zero accumulators + weight transpose/convert =================
__global__ void k_init(const float* __restrict__ W1, const float* __restrict__ W2) {
    int i = blockIdx.x * 256 + threadIdx.x;
    if (i < 2 * 4 * DIM) (&g_cacc[0][0][0])[i] = 0.f;
    if (i < 4) g_acc[i] = 0.f;
    if (i < 256 * 512) { int n = i >> 9, k = i & 511; g_w1t[i] = __float2bfloat16(W1[k * 256 + n]); }
    if (i < 128 * 256) { int n = i >> 8, k = i & 255; g_w2t[i] = __float2bfloat16(W2[k * 128 + n]); }
}

// ================= fused prep: bf16 convert + rnsub + raw column moments =================
// grid 1024, 256 threads, 16 rows of u per block
__global__ void __launch_bounds__(256) k_prep(const float* __restrict__ s,
                                              const float* __restrict__ t) {
    __shared__ float sh_rn[16];
    int tid = threadIdx.x, lane = tid & 31, wid = tid >> 5;
    if (tid < 16) sh_rn[tid] = 0.f;
    __syncthreads();

    int row0 = blockIdx.x * 16;
    int tensor = (row0 >= N_ROWS);
    const float* X = tensor ? t + (size_t)(row0 - N_ROWS) * DIM : s + (size_t)row0 * DIM;
    int c4 = tid & 127;          // float4 column index 0..127
    int rg = tid >> 7;           // 0/1
    bool inc = (c4 < KSUB / 4);  // lanes covering cols < KSUB
    bool subw = ((wid & 3) < 2); // warps that contain such lanes

    float M1[4] = {0.f, 0.f, 0.f, 0.f}, M2[4] = {0.f, 0.f, 0.f, 0.f};
    float M3[4] = {0.f, 0.f, 0.f, 0.f}, M4[4] = {0.f, 0.f, 0.f, 0.f};

#pragma unroll 8
    for (int i = 0; i < 8; i++) {
        int r = rg * 8 + i;
        float4 v = ((const float4*)(X + (size_t)r * DIM))[c4];
        __nv_bfloat162* dst = (__nv_bfloat162*)(g_ubf + (size_t)(row0 + r) * DIM);
        dst[c4 * 2]     = __floats2bfloat162_rn(v.x, v.y);
        dst[c4 * 2 + 1] = __floats2bfloat162_rn(v.z, v.w);
        float vv[4] = {v.x, v.y, v.z, v.w};
        float rn = 0.f;
#pragma unroll
        for (int j = 0; j < 4; j++) {
            float x = vv[j], x2 = x * x;
            M1[j] += x; M2[j] += x2; M3[j] += x2 * x; M4[j] += x2 * x2;
            rn += x2;
        }
        if (subw) {                 // shuffle chain only on warps that own sub lanes
            rn = inc ? rn : 0.f;
#pragma unroll
            for (int o = 16; o; o >>= 1) rn += __shfl_xor_sync(0xffffffffu, rn, o);
            if (!lane) atomicAdd(&sh_rn[r], rn);
        }
    }
    __syncthreads();
    if (tid < 16) g_rnsub[row0 + tid] = sh_rn[tid];

#pragma unroll
    for (int j = 0; j < 4; j++) {
        int c = c4 * 4 + j;
        atomicAdd(&g_cacc[tensor][0][c], M1[j]);
        atomicAdd(&g_cacc[tensor][1][c], M2[j]);
        atomicAdd(&g_cacc[tensor][2][c], M3[j]);
        atomicAdd(&g_cacc[tensor][3][c], M4[j]);
    }
}

// ================= fused: central moments + stat-diff MLP (1 block, 512 thr) =================
__global__ void k_stats(const float* __restrict__ wW1, const float* __restrict__ wb1,
                        const float* __restrict__ wW2, const float* __restrict__ wb2,
                        const float* __restrict__ wW3, const float* __restrict__ wb3,
                        float* __restrict__ out) {
    int tid = threadIdx.x;
    const float n = (float)N_ROWS;

    for (int i = tid; i < 2 * DIM; i += 512) {
        int tensor = i >> 9, c = i & 511;
        float S1 = g_cacc[tensor][0][c], S2 = g_cacc[tensor][1][c];
        float S3 = g_cacc[tensor][2][c], S4 = g_cacc[tensor][3][c];
        float m = S1 / n;
        float c2 = S2 - m * S1;
        float c3 = S3 - 3.f * m * S2 + 2.f * m * m * S1;
        float c4 = S4 - 4.f * m * S3 + 6.f * m * m * S2 - 3.f * m * m * m * S1;
        float var = c2 / (n - 1.f);
        float inv = 1.f / (sqrtf(var) + 1e-8f);
        float inv3 = inv * inv * inv;
        g_mean[tensor][c]   = m;
        g_energy[tensor][c] = S2 / n;
        g_var[tensor][c]    = var;
        g_skew[tensor][c]   = c3 * inv3 / n;
        g_kurt[tensor][c]   = c4 * inv3 * inv / n - 3.f;
    }
    __syncthreads();

    __shared__ float red[5][512];
    float l[5] = {0.f, 0.f, 0.f, 0.f, 0.f};
    if (tid < DIM) {
        l[0] = fabsf(g_mean[0][tid]   - g_mean[1][tid]);
        l[1] = fabsf(g_var[0][tid]    - g_var[1][tid]);
        l[2] = fabsf(g_kurt[0][tid]   - g_kurt[1][tid]);
        l[3] = fabsf(g_skew[0][tid]   - g_skew[1][tid]);
        l[4] = fabsf(g_energy[0][tid] - g_energy[1][tid]);
    }
#pragma unroll
    for (int k = 0; k < 5; k++) red[k][tid] = l[k];
    __syncthreads();
    for (int stride = 256; stride > 0; stride >>= 1) {
        if (tid < stride)
#pragma unroll
            for (int k = 0; k < 5; k++) red[k][tid] += red[k][tid + stride];
        __syncthreads();
    }
    __shared__ float diff[6], h1[32], h2[16];
    if (tid < 6) diff[tid] = (tid < 5) ? red[tid][0] / (float)DIM : 0.f;
    __syncthreads();
    if (tid < 32) {
        float a = wb1[tid];
#pragma unroll
        for (int k = 0; k < 6; k++) a += diff[k] * wW1[k * 32 + tid];
        h1[tid] = fmaxf(a, 0.f);
    }
    __syncthreads();
    if (tid < 16) {
        float a = wb2[tid];
#pragma unroll
        for (int k = 0; k < 32; k++) a += h1[k] * wW2[k * 16 + tid];
        h2[tid] = fmaxf(a, 0.f);
    }
    __syncthreads();
    if (tid == 0) {
        float z = wb3[0];
#pragma unroll
        for (int k = 0; k < 16; k++) z += h2[k] * wW3[k];
        float wgt = 1.f / (1.f + expf(-z));
        g_acc[3] = wgt;
        out[1] = wgt;
    }
}

// ================= discriminator MLP + BCE via HMMA =================
#define DST 40
#define H1ST 264
#define SM_A 0
#define SM_B 10240
#define SM_H1 51200
#define SM_ZP 84992
#define SM_B1 85248
#define SM_B2 86272
#define SM_W3 86784
#define DISC_SMEM 87296
#define ASTAGE (64 * DST * 2)
#define BSTAGE (256 * DST * 2)

__global__ void __launch_bounds__(256, 2) k_disc_mma(
    const float* __restrict__ b1, const float* __restrict__ b2,
    const float* __restrict__ W3, const float* __restrict__ b3) {
    extern __shared__ char smc[];
    uint32_t sm = (uint32_t)__cvta_generic_to_shared(smc);
    float* b1s = (float*)(smc + SM_B1);
    float* b2s = (float*)(smc + SM_B2);
    float* w3s = (float*)(smc + SM_W3);
    float* zps = (float*)(smc + SM_ZP);
    __nv_bfloat16* h1s = (__nv_bfloat16*)(smc + SM_H1);

    int tid = threadIdx.x, lane = tid & 31, wid = tid >> 5;
    int gid = lane >> 2, tig = lane & 3;
    int blk = blockIdx.x;
    bool srcblk = blk < 128;
    int row0 = blk * 64;

    if (tid < 256) b1s[tid] = b1[tid];
    if (tid < 128) { b2s[tid] = b2[tid]; w3s[tid] = W3[tid]; }
    if (tid < 64) zps[tid] = 0.f;

    uint32_t a_lo = (uint32_t)((lane & 15) * (DST * 2) + (lane >> 4) * 16);
    uint32_t b_lo = (uint32_t)(((lane & 7) + ((lane >> 4) * 8)) * (DST * 2) + ((lane >> 3) & 1) * 16);

    const __nv_bfloat16* gA = g_ubf + (size_t)row0 * DIM;

    auto issue1 = [&](int kt, int st) {
#pragma unroll
        for (int q = 0; q < 5; q++) {
            int c = tid + q * 256;
            if (c < 256) {
                int row = c >> 2, cg = c & 3;
                cp16(sm + SM_A + st * ASTAGE + row * (DST * 2) + cg * 16,
                     gA + (size_t)row * DIM + kt * 32 + cg * 8);
            } else {
                int b = c - 256;
                int row = b >> 2, cg = b & 3;
                cp16(sm + SM_B + st * BSTAGE + row * (DST * 2) + cg * 16,
                     g_w1t + (size_t)row * 512 + kt * 32 + cg * 8);
            }
        }
        asm volatile("cp.async.commit_group;" ::: "memory");
    };

    float acc[4][4][4];
#pragma unroll
    for (int i = 0; i < 4; i++)
#pragma unroll
        for (int j = 0; j < 4; j++)
#pragma unroll
            for (int e = 0; e < 4; e++) acc[i][j][e] = 0.f;

    issue1(0, 0);
    for (int kt = 0; kt < 16; kt++) {
        int st = kt & 1;
        if (kt < 15) { issue1(kt + 1, st ^ 1); asm volatile("cp.async.wait_group 1;" ::: "memory"); }
        else         { asm volatile("cp.async.wait_group 0;" ::: "memory"); }
        __syncthreads();
        uint32_t aS = sm + SM_A + st * ASTAGE + a_lo;
        uint32_t bS = sm + SM_B + st * BSTAGE + (uint32_t)(wid * 32) * (DST * 2) + b_lo;
#pragma unroll
        for (int ks = 0; ks < 2; ks++) {
            uint32_t kb2 = ks * 32;
            uint32_t af[4][4], bf[4][2];
#pragma unroll
            for (int mt = 0; mt < 4; mt++)
                ldm_x4(af[mt], aS + (uint32_t)(mt * 16) * (DST * 2) + kb2);
#pragma unroll
            for (int p = 0; p < 2; p++) {
                uint32_t bq[4];
                ldm_x4(bq, bS + (uint32_t)(p * 16) * (DST * 2) + kb2);
                bf[2 * p][0] = bq[0]; bf[2 * p][1] = bq[1];
                bf[2 * p + 1][0] = bq[2]; bf[2 * p + 1][1] = bq[3];
            }
#pragma unroll
            for (int mt = 0; mt < 4; mt++)
#pragma unroll
                for (int nt = 0; nt < 4; nt++)
                    mma16816(acc[mt][nt], af[mt], bf[nt]);
        }
        __syncthreads();
    }

#pragma unroll
    for (int mt = 0; mt < 4; mt++) {
#pragma unroll
        for (int nt = 0; nt < 4; nt++) {
            int col0 = wid * 32 + nt * 8 + 2 * tig;
#pragma unroll
            for (int e = 0; e < 4; e++) {
                int row = mt * 16 + gid + ((e >= 2) ? 8 : 0);
                int col = col0 + (e & 1);
                float v = fmaxf(acc[mt][nt][e] + b1s[col], 0.f);
                h1s[row * H1ST + col] = __float2bfloat16(v);
            }
        }
    }
    __syncthreads();

    auto issue2 = [&](int kt, int st) {
#pragma unroll
        for (int q = 0; q < 2; q++) {
            int c = tid + q * 256;
            int row = c >> 2, cg = c & 3;
            cp16(sm + SM_B + st * BSTAGE + row * (DST * 2) + cg * 16,
                 g_w2t + (size_t)row * 256 + kt * 32 + cg * 8);
        }
        asm volatile("cp.async.commit_group;" ::: "memory");
    };

#pragma unroll
    for (int i = 0; i < 4; i++)
#pragma unroll
        for (int j = 0; j < 4; j++)
#pragma unroll
            for (int e = 0; e < 4; e++) acc[i][j][e] = 0.f;

    uint32_t a_lo2 = (uint32_t)((lane & 15) * (H1ST * 2) + (lane >> 4) * 16);
    issue2(0, 0);
    for (int kt = 0; kt < 8; kt++) {
        int st = kt & 1;
        if (kt < 7) { issue2(kt + 1, st ^ 1); asm volatile("cp.async.wait_group 1;" ::: "memory"); }
        else        { asm volatile("cp.async.wait_group 0;" ::: "memory"); }
        __syncthreads();
        if (wid < 4) {
            uint32_t aS = sm + SM_H1 + a_lo2 + (uint32_t)(kt * 64);
            uint32_t bS = sm + SM_B + st * BSTAGE + (uint32_t)(wid * 32) * (DST * 2) + b_lo;
#pragma unroll
            for (int ks = 0; ks < 2; ks++) {
                uint32_t kb2 = ks * 32;
                uint32_t af[4][4], bf[4][2];
#pragma unroll
                for (int mt = 0; mt < 4; mt++)
                    ldm_x4(af[mt], aS + (uint32_t)(mt * 16) * (H1ST * 2) + kb2);
#pragma unroll
                for (int p = 0; p < 2; p++) {
                    uint32_t bq[4];
                    ldm_x4(bq, bS + (uint32_t)(p * 16) * (DST * 2) + kb2);
                    bf[2 * p][0] = bq[0]; bf[2 * p][1] = bq[1];
                    bf[2 * p + 1][0] = bq[2]; bf[2 * p + 1][1] = bq[3];
                }
#pragma unroll
                for (int mt = 0; mt < 4; mt++)
#pragma unroll
                    for (int nt = 0; nt < 4; nt++)
                        mma16816(acc[mt][nt], af[mt], bf[nt]);
            }
        }
        __syncthreads();
    }

    if (wid < 4) {
#pragma unroll
        for (int mt = 0; mt < 4; mt++) {
            float zp0 = 0.f, zp1 = 0.f;
#pragma unroll
            for (int nt = 0; nt < 4; nt++) {
                int col0 = wid * 32 + nt * 8 + 2 * tig;
                float w30 = w3s[col0], w31 = w3s[col0 + 1];
                float bb0 = b2s[col0], bb1 = b2s[col0 + 1];
                zp0 += fmaxf(acc[mt][nt][0] + bb0, 0.f) * w30
                     + fmaxf(acc[mt][nt][1] + bb1, 0.f) * w31;
                zp1 += fmaxf(acc[mt][nt][2] + bb0, 0.f) * w30
                     + fmaxf(acc[mt][nt][3] + bb1, 0.f) * w31;
            }
            atomicAdd(&zps[mt * 16 + gid], zp0);
            atomicAdd(&zps[mt * 16 + gid + 8], zp1);
        }
    }
    __syncthreads();

    if (tid < 64) {
        float z = zps[tid] + b3[0];
        float p = 1.f / (1.f + expf(-z));
        float term = srcblk ? fmaxf(logf(p), -100.f) : fmaxf(logf(1.f - p), -100.f);
#pragma unroll
        for (int o = 16; o; o >>= 1) term += __shfl_xor_sync(0xffffffffu, term, o);
        if (!lane) zps[wid] = term;
    }
    __syncthreads();
    if (tid == 0) atomicAdd(&g_acc[srcblk ? 1 : 2], zps[0] + zps[1]);
}

// ================= MMD: K=160 screening Gram, 3-buffer 1-sync pipeline =================
#define AST 40                           // smem row stride (bf16): 80 B, conflict-free
#define STG (128 * AST * 2)              // 10240 B per stage per matrix
#define OFF_B  (3 * STG)                 // 30720
#define OFF_RNI (6 * STG)                // 61440
#define OFF_RNJ (OFF_RNI + 512)
#define OFF_RS  (OFF_RNJ + 512)
#define MMD_SMEM (OFF_RS + 32)           // 62496
#define NTILE 128
#define NTRI  (NTILE * (NTILE + 1) / 2)  // 8256
#define NSTAGE (KSUB / 32)               // 5

__global__ void __launch_bounds__(256, 2) k_mmd_hmma(const float* __restrict__ s,
                                                     const float* __restrict__ t) {
    int idx = blockIdx.x;
    int by = (int)(128.5f - sqrtf(128.5f * 128.5f - 2.0f * (float)idx));
    while ((by + 1) * NTILE - ((by + 1) * by) / 2 <= idx) by++;
    while (by * NTILE - (by * (by - 1)) / 2 > idx) by--;
    int bx = by + (idx - (by * NTILE - (by * (by - 1)) / 2));

    extern __shared__ char smc[];
    uint32_t sm = (uint32_t)__cvta_generic_to_shared(smc);
    float* rni_s = (float*)(smc + OFF_RNI);
    float* rnj_s = (float*)(smc + OFF_RNJ);
    float* rsum  = (float*)(smc + OFF_RS);

    int tid = threadIdx.x, lane = tid & 31, wid = tid >> 5;
    int wm = wid & 1, wn = wid >> 1;
    int gid = lane >> 2, tig = lane & 3;
    int arow0 = by * 128, brow0 = bx * 128;

    if (tid < 128) {
        rni_s[tid] = g_rnsub[arow0 + tid];
        rnj_s[tid] = g_rnsub[brow0 + tid];
    }

    const __nv_bfloat16* gA = g_ubf + (size_t)arow0 * DIM;
    const __nv_bfloat16* gB = g_ubf + (size_t)brow0 * DIM;

    uint32_t a_lo = (uint32_t)((lane & 15) * (AST * 2) + (lane >> 4) * 16);
    uint32_t b_lo = (uint32_t)(((lane & 7) + ((lane >> 4) * 8)) * (AST * 2) + ((lane >> 3) & 1) * 16);

    float acc[4][4][4];
#pragma unroll
    for (int i = 0; i < 4; i++)
#pragma unroll
        for (int j = 0; j < 4; j++)
#pragma unroll
            for (int e = 0; e < 4; e++) acc[i][j][e] = 0.f;

    auto issue = [&](int kt, int buf) {
#pragma unroll
        for (int q = 0; q < 2; q++) {
            int c = tid + q * 256;           // 0..511 16B-chunks
            int row = c >> 2, cg = c & 3;
            size_t goff = (size_t)row * DIM + (size_t)kt * 32 + cg * 8;
            uint32_t soff = (uint32_t)(buf * STG + row * (AST * 2) + cg * 16);
            cp16(sm + soff, gA + goff);
            cp16(sm + OFF_B + soff, gB + goff);
        }
        asm volatile("cp.async.commit_group;" ::: "memory");
    };

    issue(0, 0);
    issue(1, 1);
#pragma unroll
    for (int kt = 0; kt < NSTAGE; kt++) {
        int buf = kt % 3;
        if (kt < NSTAGE - 1) asm volatile("cp.async.wait_group 1;" ::: "memory");
        else                 asm volatile("cp.async.wait_group 0;" ::: "memory");
        __syncthreads();                     // single barrier per stage
        if (kt + 2 < NSTAGE) issue(kt + 2, (kt + 2) % 3);

        uint32_t aS = sm + buf * STG + (uint32_t)(wm * 64) * (AST * 2) + a_lo;
        uint32_t bS = sm + OFF_B + buf * STG + (uint32_t)(wn * 32) * (AST * 2) + b_lo;
#pragma unroll
        for (int ks = 0; ks < 2; ks++) {
            uint32_t kb2 = ks * 32;
            uint32_t af[4][4], bf[4][2];
#pragma unroll
            for (int mt = 0; mt < 4; mt++)
                ldm_x4(af[mt], aS + (uint32_t)(mt * 16) * (AST * 2) + kb2);
#pragma unroll
            for (int p = 0; p < 2; p++) {
                uint32_t bq[4];
                ldm_x4(bq, bS + (uint32_t)(p * 16) * (AST * 2) + kb2);
                bf[2 * p][0] = bq[0]; bf[2 * p][1] = bq[1];
                bf[2 * p + 1][0] = bq[2]; bf[2 * p + 1][1] = bq[3];
            }
#pragma unroll
            for (int mt = 0; mt < 4; mt++)
#pragma unroll
                for (int nt = 0; nt < 4; nt++)
                    mma16816(acc[mt][nt], af[mt], bf[nt]);
        }
    }

    bool diag = (bx == by);
    float sgn = ((by < 64) == (bx < 64)) ? 1.f : -1.f;
    float local = 0.f;

#pragma unroll
    for (int mt = 0; mt < 4; mt++) {
        int li0 = wm * 64 + mt * 16 + gid;
        float rn0 = rni_s[li0], rn1 = rni_s[li0 + 8];
#pragma unroll
        for (int nt = 0; nt < 4; nt++) {
            int lj0 = wn * 32 + nt * 8 + 2 * tig;
#pragma unroll
            for (int e = 0; e < 4; e++) {
                int li = li0 + ((e >= 2) ? 8 : 0);
                int lj = lj0 + (e & 1);
                float rn_i = (e >= 2) ? rn1 : rn0;
                float rj = rnj_s[lj];
                float d2s = rn_i + rj - 2.f * acc[mt][nt][e];
                int gi = arow0 + li, gj = brow0 + lj;
                float wgt = diag ? ((gj > gi) ? 2.f : 0.f) : 2.f;
                if (wgt != 0.f && d2s < 164.f + 0.01f * (rn_i + rj)) {
                    const float* pi = (gi < N_ROWS) ? s + (size_t)gi * DIM
                                                    : t + (size_t)(gi - N_ROWS) * DIM;
                    const float* pj = (gj < N_ROWS) ? s + (size_t)gj * DIM
                                                    : t + (size_t)(gj - N_ROWS) * DIM;
                    float a2 = 0.f;
                    for (int k = 0; k < DIM; k += 4) {
                        float4 a = *(const float4*)(pi + k);
                        float4 b = *(const float4*)(pj + k);
                        float e0 = a.x - b.x, e1 = a.y - b.y, e2 = a.z - b.z, e3 = a.w - b.w;
                        a2 += e0 * e0 + e1 * e1 + e2 * e2 + e3 * e3;
                    }
                    local += wgt * expf(-0.5f * a2);
                }
            }
        }
    }
    local *= sgn;
#pragma unroll
    for (int o = 16; o; o >>= 1) local += __shfl_xor_sync(0xffffffffu, local, o);
    if (!lane) rsum[wid] = local;
    __syncthreads();
    if (tid == 0) {
        float tot = 0.f;
#pragma unroll
        for (int i = 0; i < 8; i++) tot += rsum[i];
        if (tot != 0.f) atomicAdd(&g_acc[0], tot);
    }
}

// ================= final combine =================
__global__ void k_final(float* __restrict__ out) {
    float mmd = (g_acc[0] + (float)TWO_N) / ((float)N_ROWS * (float)N_ROWS);
    float adv = -g_acc[1] / (float)N_ROWS - g_acc[2] / (float)N_ROWS;
    float w = g_acc[3];
    out[0] = w * mmd + (1.f - w) * adv;
}

// ================= launch (single stream) =================
extern "C" void kernel_launch(void* const* d_in, const int* in_sizes, int n_in,
                              void* d_out, int out_size) {
    const float* s   = (const float*)d_in[0];
    const float* t   = (const float*)d_in[1];
    const float* dW1 = (const float*)d_in[2];
    const float* db1 = (const float*)d_in[3];
    const float* dW2 = (const float*)d_in[4];
    const float* db2 = (const float*)d_in[5];
    const float* dW3 = (const float*)d_in[6];
    const float* db3 = (const float*)d_in[7];
    const float* wW1 = (const float*)d_in[8];
    const float* wb1 = (const float*)d_in[9];
    const float* wW2 = (const float*)d_in[10];
    const float* wb2 = (const float*)d_in[11];
    const float* wW3 = (const float*)d_in[12];
    const float* wb3 = (const float*)d_in[13];
    float* out = (float*)d_out;

    cudaFuncSetAttribute(k_disc_mma, cudaFuncAttributeMaxDynamicSharedMemorySize, DISC_SMEM);
    cudaFuncSetAttribute(k_mmd_hmma, cudaFuncAttributeMaxDynamicSharedMemorySize, MMD_SMEM);

    k_init<<<512, 256>>>(dW1, dW2);
    k_prep<<<TWO_N / 16, 256>>>(s, t);
    k_stats<<<1, 512>>>(wW1, wb1, wW2, wb2, wW3, wb3, out);
    k_disc_mma<<<256, 256, DISC_SMEM>>>(db1, db2, dW3, db3);
    k_mmd_hmma<<<NTRI, 256, MMD_SMEM>>>(s, t);
    k_final<<<1, 1>>>(out);
}

// round 15
// speedup vs baseline: 1.1025x; 1.1025x over previous
#include <cuda_runtime.h>
#include <cuda_bf16.h>
#include <math.h>
#include <stdint.h>

#define N_ROWS 8192
#define DIM    512
#define KSUB   160          // screening subspace (first 160 dims)
#define TWO_N  16384

// ================= device scratch =================
__device__ float g_mean[2][DIM];
__device__ float g_energy[2][DIM];
__device__ float g_var[2][DIM];
__device__ float g_kurt[2][DIM];
__device__ float g_skew[2][DIM];
__device__ float g_rnsub[TWO_N];             // squared norm over first KSUB dims
__device__ float g_cacc[2][4][DIM];          // raw moment partials S1..S4
__device__ float g_acc[4];                   // 0 mmd-sum, 1 log(p) src, 2 log(1-p) tgt, 3 weight
__device__ __nv_bfloat16 g_ubf[(size_t)TWO_N * DIM];   // bf16 copy of u=[s;t], full 512 dims
__device__ __nv_bfloat16 g_w1t[256 * 512];   // W1^T bf16 [n][k]
__device__ __nv_bfloat16 g_w2t[128 * 256];   // W2^T bf16 [n][k]

// ================= helpers =================
__device__ __forceinline__ void cp16(uint32_t dst_smem, const void* src) {
    asm volatile("cp.async.cg.shared.global [%0], [%1], 16;" :: "r"(dst_smem), "l"(src));
}
__device__ __forceinline__ void mma16816(float* c, const uint32_t* a, const uint32_t* b) {
    asm volatile(
        "mma.sync.aligned.m16n8k16.row.col.f32.bf16.bf16.f32 "
        "{%0,%1,%2,%3}, {%4,%5,%6,%7}, {%8,%9}, {%0,%1,%2,%3};"
        : "+f"(c[0]), "+f"(c[1]), "+f"(c[2]), "+f"(c[3])
        : "r"(a[0]), "r"(a[1]), "r"(a[2]), "r"(a[3]), "r"(b[0]), "r"(b[1]));
}
__device__ __forceinline__ void ldm_x4(uint32_t* r, uint32_t addr) {
    asm volatile("ldmatrix.sync.aligned.m8n8.x4.shared.b16 {%0,%1,%2,%3}, [%4];"
        : "=r"(r[0]), "=r"(r[1]), "=r"(r[2]), "=r"(r[3]) : "r"(addr));
}

// ================= init: zero accumulators + weight transpose/convert =================
__global__ void k_init(const float* __restrict__ W1, const float* __restrict__ W2) {
    int i = blockIdx.x * 256 + threadIdx.x;
    if (i < 2 * 4 * DIM) (&g_cacc[0][0][0])[i] = 0.f;
    if (i < 4) g_acc[i] = 0.f;
    if (i < 256 * 512) { int n = i >> 9, k = i & 511; g_w1t[i] = __float2bfloat16(W1[k * 256 + n]); }
    if (i < 128 * 256) { int n = i >> 8, k = i & 255; g_w2t[i] = __float2bfloat16(W2[k * 128 + n]); }
}

// ================= fused prep: bf16 convert + rnsub + raw column moments =================
// grid 512, 256 threads, 32 rows of u per block (R12-proven shape)
__global__ void __launch_bounds__(256) k_prep(const float* __restrict__ s,
                                              const float* __restrict__ t) {
    __shared__ float sh_rn[32];
    int tid = threadIdx.x, lane = tid & 31, wid = tid >> 5;
    if (tid < 32) sh_rn[tid] = 0.f;
    __syncthreads();

    int row0 = blockIdx.x * 32;
    int tensor = (row0 >= N_ROWS);
    const float* X = tensor ? t + (size_t)(row0 - N_ROWS) * DIM : s + (size_t)row0 * DIM;
    int c4 = tid & 127;          // float4 column index 0..127
    int rg = tid >> 7;           // 0/1
    bool inc = (c4 < KSUB / 4);  // lanes covering cols < KSUB
    bool subw = ((wid & 3) < 2); // warps that contain such lanes

    float M1[4] = {0.f, 0.f, 0.f, 0.f}, M2[4] = {0.f, 0.f, 0.f, 0.f};
    float M3[4] = {0.f, 0.f, 0.f, 0.f}, M4[4] = {0.f, 0.f, 0.f, 0.f};

#pragma unroll 4
    for (int i = 0; i < 16; i++) {
        int r = rg * 16 + i;
        float4 v = ((const float4*)(X + (size_t)r * DIM))[c4];
        __nv_bfloat162* dst = (__nv_bfloat162*)(g_ubf + (size_t)(row0 + r) * DIM);
        dst[c4 * 2]     = __floats2bfloat162_rn(v.x, v.y);
        dst[c4 * 2 + 1] = __floats2bfloat162_rn(v.z, v.w);
        float vv[4] = {v.x, v.y, v.z, v.w};
        float rn = 0.f;
#pragma unroll
        for (int j = 0; j < 4; j++) {
            float x = vv[j], x2 = x * x;
            M1[j] += x; M2[j] += x2; M3[j] += x2 * x; M4[j] += x2 * x2;
            rn += x2;
        }
        if (subw) {                 // shuffle chain only on warps that own sub lanes
            rn = inc ? rn : 0.f;
#pragma unroll
            for (int o = 16; o; o >>= 1) rn += __shfl_xor_sync(0xffffffffu, rn, o);
            if (!lane) atomicAdd(&sh_rn[r], rn);
        }
    }
    __syncthreads();
    if (tid < 32) g_rnsub[row0 + tid] = sh_rn[tid];

#pragma unroll
    for (int j = 0; j < 4; j++) {
        int c = c4 * 4 + j;
        atomicAdd(&g_cacc[tensor][0][c], M1[j]);
        atomicAdd(&g_cacc[tensor][1][c], M2[j]);
        atomicAdd(&g_cacc[tensor][2][c], M3[j]);
        atomicAdd(&g_cacc[tensor][3][c], M4[j]);
    }
}

// ================= fused: central moments + stat-diff MLP (1 block, 512 thr) =================
__global__ void k_stats(const float* __restrict__ wW1, const float* __restrict__ wb1,
                        const float* __restrict__ wW2, const float* __restrict__ wb2,
                        const float* __restrict__ wW3, const float* __restrict__ wb3,
                        float* __restrict__ out) {
    int tid = threadIdx.x;
    const float n = (float)N_ROWS;

    for (int i = tid; i < 2 * DIM; i += 512) {
        int tensor = i >> 9, c = i & 511;
        float S1 = g_cacc[tensor][0][c], S2 = g_cacc[tensor][1][c];
        float S3 = g_cacc[tensor][2][c], S4 = g_cacc[tensor][3][c];
        float m = S1 / n;
        float c2 = S2 - m * S1;
        float c3 = S3 - 3.f * m * S2 + 2.f * m * m * S1;
        float c4 = S4 - 4.f * m * S3 + 6.f * m * m * S2 - 3.f * m * m * m * S1;
        float var = c2 / (n - 1.f);
        float inv = 1.f / (sqrtf(var) + 1e-8f);
        float inv3 = inv * inv * inv;
        g_mean[tensor][c]   = m;
        g_energy[tensor][c] = S2 / n;
        g_var[tensor][c]    = var;
        g_skew[tensor][c]   = c3 * inv3 / n;
        g_kurt[tensor][c]   = c4 * inv3 * inv / n - 3.f;
    }
    __syncthreads();

    __shared__ float red[5][512];
    float l[5] = {0.f, 0.f, 0.f, 0.f, 0.f};
    if (tid < DIM) {
        l[0] = fabsf(g_mean[0][tid]   - g_mean[1][tid]);
        l[1] = fabsf(g_var[0][tid]    - g_var[1][tid]);
        l[2] = fabsf(g_kurt[0][tid]   - g_kurt[1][tid]);
        l[3] = fabsf(g_skew[0][tid]   - g_skew[1][tid]);
        l[4] = fabsf(g_energy[0][tid] - g_energy[1][tid]);
    }
#pragma unroll
    for (int k = 0; k < 5; k++) red[k][tid] = l[k];
    __syncthreads();
    for (int stride = 256; stride > 0; stride >>= 1) {
        if (tid < stride)
#pragma unroll
            for (int k = 0; k < 5; k++) red[k][tid] += red[k][tid + stride];
        __syncthreads();
    }
    __shared__ float diff[6], h1[32], h2[16];
    if (tid < 6) diff[tid] = (tid < 5) ? red[tid][0] / (float)DIM : 0.f;
    __syncthreads();
    if (tid < 32) {
        float a = wb1[tid];
#pragma unroll
        for (int k = 0; k < 6; k++) a += diff[k] * wW1[k * 32 + tid];
        h1[tid] = fmaxf(a, 0.f);
    }
    __syncthreads();
    if (tid < 16) {
        float a = wb2[tid];
#pragma unroll
        for (int k = 0; k < 32; k++) a += h1[k] * wW2[k * 16 + tid];
        h2[tid] = fmaxf(a, 0.f);
    }
    __syncthreads();
    if (tid == 0) {
        float z = wb3[0];
#pragma unroll
        for (int k = 0; k < 16; k++) z += h2[k] * wW3[k];
        float wgt = 1.f / (1.f + expf(-z));
        g_acc[3] = wgt;
        out[1] = wgt;
    }
}

// ================= discriminator MLP + BCE via HMMA =================
#define DST 40
#define H1ST 264
#define SM_A 0
#define SM_B 10240
#define SM_H1 51200
#define SM_ZP 84992
#define SM_B1 85248
#define SM_B2 86272
#define SM_W3 86784
#define DISC_SMEM 87296
#define ASTAGE (64 * DST * 2)
#define BSTAGE (256 * DST * 2)

__global__ void __launch_bounds__(256, 2) k_disc_mma(
    const float* __restrict__ b1, const float* __restrict__ b2,
    const float* __restrict__ W3, const float* __restrict__ b3) {
    extern __shared__ char smc[];
    uint32_t sm = (uint32_t)__cvta_generic_to_shared(smc);
    float* b1s = (float*)(smc + SM_B1);
    float* b2s = (float*)(smc + SM_B2);
    float* w3s = (float*)(smc + SM_W3);
    float* zps = (float*)(smc + SM_ZP);
    __nv_bfloat16* h1s = (__nv_bfloat16*)(smc + SM_H1);

    int tid = threadIdx.x, lane = tid & 31, wid = tid >> 5;
    int gid = lane >> 2, tig = lane & 3;
    int blk = blockIdx.x;
    bool srcblk = blk < 128;
    int row0 = blk * 64;

    if (tid < 256) b1s[tid] = b1[tid];
    if (tid < 128) { b2s[tid] = b2[tid]; w3s[tid] = W3[tid]; }
    if (tid < 64) zps[tid] = 0.f;

    uint32_t a_lo = (uint32_t)((lane & 15) * (DST * 2) + (lane >> 4) * 16);
    uint32_t b_lo = (uint32_t)(((lane & 7) + ((lane >> 4) * 8)) * (DST * 2) + ((lane >> 3) & 1) * 16);

    const __nv_bfloat16* gA = g_ubf + (size_t)row0 * DIM;

    auto issue1 = [&](int kt, int st) {
#pragma unroll
        for (int q = 0; q < 5; q++) {
            int c = tid + q * 256;
            if (c < 256) {
                int row = c >> 2, cg = c & 3;
                cp16(sm + SM_A + st * ASTAGE + row * (DST * 2) + cg * 16,
                     gA + (size_t)row * DIM + kt * 32 + cg * 8);
            } else {
                int b = c - 256;
                int row = b >> 2, cg = b & 3;
                cp16(sm + SM_B + st * BSTAGE + row * (DST * 2) + cg * 16,
                     g_w1t + (size_t)row * 512 + kt * 32 + cg * 8);
            }
        }
        asm volatile("cp.async.commit_group;" ::: "memory");
    };

    float acc[4][4][4];
#pragma unroll
    for (int i = 0; i < 4; i++)
#pragma unroll
        for (int j = 0; j < 4; j++)
#pragma unroll
            for (int e = 0; e < 4; e++) acc[i][j][e] = 0.f;

    issue1(0, 0);
    for (int kt = 0; kt < 16; kt++) {
        int st = kt & 1;
        if (kt < 15) { issue1(kt + 1, st ^ 1); asm volatile("cp.async.wait_group 1;" ::: "memory"); }
        else         { asm volatile("cp.async.wait_group 0;" ::: "memory"); }
        __syncthreads();
        uint32_t aS = sm + SM_A + st * ASTAGE + a_lo;
        uint32_t bS = sm + SM_B + st * BSTAGE + (uint32_t)(wid * 32) * (DST * 2) + b_lo;
#pragma unroll
        for (int ks = 0; ks < 2; ks++) {
            uint32_t kb2 = ks * 32;
            uint32_t af[4][4], bf[4][2];
#pragma unroll
            for (int mt = 0; mt < 4; mt++)
                ldm_x4(af[mt], aS + (uint32_t)(mt * 16) * (DST * 2) + kb2);
#pragma unroll
            for (int p = 0; p < 2; p++) {
                uint32_t bq[4];
                ldm_x4(bq, bS + (uint32_t)(p * 16) * (DST * 2) + kb2);
                bf[2 * p][0] = bq[0]; bf[2 * p][1] = bq[1];
                bf[2 * p + 1][0] = bq[2]; bf[2 * p + 1][1] = bq[3];
            }
#pragma unroll
            for (int mt = 0; mt < 4; mt++)
#pragma unroll
                for (int nt = 0; nt < 4; nt++)
                    mma16816(acc[mt][nt], af[mt], bf[nt]);
        }
        __syncthreads();
    }

#pragma unroll
    for (int mt = 0; mt < 4; mt++) {
#pragma unroll
        for (int nt = 0; nt < 4; nt++) {
            int col0 = wid * 32 + nt * 8 + 2 * tig;
#pragma unroll
            for (int e = 0; e < 4; e++) {
                int row = mt * 16 + gid + ((e >= 2) ? 8 : 0);
                int col = col0 + (e & 1);
                float v = fmaxf(acc[mt][nt][e] + b1s[col], 0.f);
                h1s[row * H1ST + col] = __float2bfloat16(v);
            }
        }
    }
    __syncthreads();

    auto issue2 = [&](int kt, int st) {
#pragma unroll
        for (int q = 0; q < 2; q++) {
            int c = tid + q * 256;
            int row = c >> 2, cg = c & 3;
            cp16(sm + SM_B + st * BSTAGE + row * (DST * 2) + cg * 16,
                 g_w2t + (size_t)row * 256 + kt * 32 + cg * 8);
        }
        asm volatile("cp.async.commit_group;" ::: "memory");
    };

#pragma unroll
    for (int i = 0; i < 4; i++)
#pragma unroll
        for (int j = 0; j < 4; j++)
#pragma unroll
            for (int e = 0; e < 4; e++) acc[i][j][e] = 0.f;

    uint32_t a_lo2 = (uint32_t)((lane & 15) * (H1ST * 2) + (lane >> 4) * 16);
    issue2(0, 0);
    for (int kt = 0; kt < 8; kt++) {
        int st = kt & 1;
        if (kt < 7) { issue2(kt + 1, st ^ 1); asm volatile("cp.async.wait_group 1;" ::: "memory"); }
        else        { asm volatile("cp.async.wait_group 0;" ::: "memory"); }
        __syncthreads();
        if (wid < 4) {
            uint32_t aS = sm + SM_H1 + a_lo2 + (uint32_t)(kt * 64);
            uint32_t bS = sm + SM_B + st * BSTAGE + (uint32_t)(wid * 32) * (DST * 2) + b_lo;
#pragma unroll
            for (int ks = 0; ks < 2; ks++) {
                uint32_t kb2 = ks * 32;
                uint32_t af[4][4], bf[4][2];
#pragma unroll
                for (int mt = 0; mt < 4; mt++)
                    ldm_x4(af[mt], aS + (uint32_t)(mt * 16) * (H1ST * 2) + kb2);
#pragma unroll
                for (int p = 0; p < 2; p++) {
                    uint32_t bq[4];
                    ldm_x4(bq, bS + (uint32_t)(p * 16) * (DST * 2) + kb2);
                    bf[2 * p][0] = bq[0]; bf[2 * p][1] = bq[1];
                    bf[2 * p + 1][0] = bq[2]; bf[2 * p + 1][1] = bq[3];
                }
#pragma unroll
                for (int mt = 0; mt < 4; mt++)
#pragma unroll
                    for (int nt = 0; nt < 4; nt++)
                        mma16816(acc[mt][nt], af[mt], bf[nt]);
            }
        }
        __syncthreads();
    }

    if (wid < 4) {
#pragma unroll
        for (int mt = 0; mt < 4; mt++) {
            float zp0 = 0.f, zp1 = 0.f;
#pragma unroll
            for (int nt = 0; nt < 4; nt++) {
                int col0 = wid * 32 + nt * 8 + 2 * tig;
                float w30 = w3s[col0], w31 = w3s[col0 + 1];
                float bb0 = b2s[col0], bb1 = b2s[col0 + 1];
                zp0 += fmaxf(acc[mt][nt][0] + bb0, 0.f) * w30
                     + fmaxf(acc[mt][nt][1] + bb1, 0.f) * w31;
                zp1 += fmaxf(acc[mt][nt][2] + bb0, 0.f) * w30
                     + fmaxf(acc[mt][nt][3] + bb1, 0.f) * w31;
            }
            atomicAdd(&zps[mt * 16 + gid], zp0);
            atomicAdd(&zps[mt * 16 + gid + 8], zp1);
        }
    }
    __syncthreads();

    if (tid < 64) {
        float z = zps[tid] + b3[0];
        float p = 1.f / (1.f + expf(-z));
        float term = srcblk ? fmaxf(logf(p), -100.f) : fmaxf(logf(1.f - p), -100.f);
#pragma unroll
        for (int o = 16; o; o >>= 1) term += __shfl_xor_sync(0xffffffffu, term, o);
        if (!lane) zps[wid] = term;
    }
    __syncthreads();
    if (tid == 0) atomicAdd(&g_acc[srcblk ? 1 : 2], zps[0] + zps[1]);
}

// ================= MMD: K=160 screening Gram, 3-buffer 1-sync pipeline =================
#define AST 40                           // smem row stride (bf16): 80 B, conflict-free
#define STG (128 * AST * 2)              // 10240 B per stage per matrix
#define OFF_B  (3 * STG)                 // 30720
#define OFF_RNI (6 * STG)                // 61440
#define OFF_RNJ (OFF_RNI + 512)
#define OFF_RS  (OFF_RNJ + 512)
#define MMD_SMEM (OFF_RS + 32)           // 62496
#define NTILE 128
#define NTRI  (NTILE * (NTILE + 1) / 2)  // 8256
#define NSTAGE (KSUB / 32)               // 5

__global__ void __launch_bounds__(256, 2) k_mmd_hmma(const float* __restrict__ s,
                                                     const float* __restrict__ t) {
    int idx = blockIdx.x;
    int by = (int)(128.5f - sqrtf(128.5f * 128.5f - 2.0f * (float)idx));
    while ((by + 1) * NTILE - ((by + 1) * by) / 2 <= idx) by++;
    while (by * NTILE - (by * (by - 1)) / 2 > idx) by--;
    int bx = by + (idx - (by * NTILE - (by * (by - 1)) / 2));

    extern __shared__ char smc[];
    uint32_t sm = (uint32_t)__cvta_generic_to_shared(smc);
    float* rni_s = (float*)(smc + OFF_RNI);
    float* rnj_s = (float*)(smc + OFF_RNJ);
    float* rsum  = (float*)(smc + OFF_RS);

    int tid = threadIdx.x, lane = tid & 31, wid = tid >> 5;
    int wm = wid & 1, wn = wid >> 1;
    int gid = lane >> 2, tig = lane & 3;
    int arow0 = by * 128, brow0 = bx * 128;

    if (tid < 128) {
        rni_s[tid] = g_rnsub[arow0 + tid];
        rnj_s[tid] = g_rnsub[brow0 + tid];
    }

    const __nv_bfloat16* gA = g_ubf + (size_t)arow0 * DIM;
    const __nv_bfloat16* gB = g_ubf + (size_t)brow0 * DIM;

    uint32_t a_lo = (uint32_t)((lane & 15) * (AST * 2) + (lane >> 4) * 16);
    uint32_t b_lo = (uint32_t)(((lane & 7) + ((lane >> 4) * 8)) * (AST * 2) + ((lane >> 3) & 1) * 16);

    float acc[4][4][4];
#pragma unroll
    for (int i = 0; i < 4; i++)
#pragma unroll
        for (int j = 0; j < 4; j++)
#pragma unroll
            for (int e = 0; e < 4; e++) acc[i][j][e] = 0.f;

    auto issue = [&](int kt, int buf) {
#pragma unroll
        for (int q = 0; q < 2; q++) {
            int c = tid + q * 256;           // 0..511 16B-chunks
            int row = c >> 2, cg = c & 3;
            size_t goff = (size_t)row * DIM + (size_t)kt * 32 + cg * 8;
            uint32_t soff = (uint32_t)(buf * STG + row * (AST * 2) + cg * 16);
            cp16(sm + soff, gA + goff);
            cp16(sm + OFF_B + soff, gB + goff);
        }
        asm volatile("cp.async.commit_group;" ::: "memory");
    };

    issue(0, 0);
    issue(1, 1);
#pragma unroll
    for (int kt = 0; kt < NSTAGE; kt++) {
        int buf = kt % 3;
        if (kt < NSTAGE - 1) asm volatile("cp.async.wait_group 1;" ::: "memory");
        else                 asm volatile("cp.async.wait_group 0;" ::: "memory");
        __syncthreads();                     // single barrier per stage
        if (kt + 2 < NSTAGE) issue(kt + 2, (kt + 2) % 3);

        uint32_t aS = sm + buf * STG + (uint32_t)(wm * 64) * (AST * 2) + a_lo;
        uint32_t bS = sm + OFF_B + buf * STG + (uint32_t)(wn * 32) * (AST * 2) + b_lo;
#pragma unroll
        for (int ks = 0; ks < 2; ks++) {
            uint32_t kb2 = ks * 32;
            uint32_t af[4][4], bf[4][2];
#pragma unroll
            for (int mt = 0; mt < 4; mt++)
                ldm_x4(af[mt], aS + (uint32_t)(mt * 16) * (AST * 2) + kb2);
#pragma unroll
            for (int p = 0; p < 2; p++) {
                uint32_t bq[4];
                ldm_x4(bq, bS + (uint32_t)(p * 16) * (AST * 2) + kb2);
                bf[2 * p][0] = bq[0]; bf[2 * p][1] = bq[1];
                bf[2 * p + 1][0] = bq[2]; bf[2 * p + 1][1] = bq[3];
            }
#pragma unroll
            for (int mt = 0; mt < 4; mt++)
#pragma unroll
                for (int nt = 0; nt < 4; nt++)
                    mma16816(acc[mt][nt], af[mt], bf[nt]);
        }
    }

    bool diag = (bx == by);
    float sgn = ((by < 64) == (bx < 64)) ? 1.f : -1.f;
    float local = 0.f;

#pragma unroll
    for (int mt = 0; mt < 4; mt++) {
        int li0 = wm * 64 + mt * 16 + gid;
        float rn0 = rni_s[li0], rn1 = rni_s[li0 + 8];
#pragma unroll
        for (int nt = 0; nt < 4; nt++) {
            int lj0 = wn * 32 + nt * 8 + 2 * tig;
#pragma unroll
            for (int e = 0; e < 4; e++) {
                int li = li0 + ((e >= 2) ? 8 : 0);
                int lj = lj0 + (e & 1);
                float rn_i = (e >= 2) ? rn1 : rn0;
                float rj = rnj_s[lj];
                float d2s = rn_i + rj - 2.f * acc[mt][nt][e];
                int gi = arow0 + li, gj = brow0 + lj;
                float wgt = diag ? ((gj > gi) ? 2.f : 0.f) : 2.f;
                if (wgt != 0.f && d2s < 164.f + 0.01f * (rn_i + rj)) {
                    const float* pi = (gi < N_ROWS) ? s + (size_t)gi * DIM
                                                    : t + (size_t)(gi - N_ROWS) * DIM;
                    const float* pj = (gj < N_ROWS) ? s + (size_t)gj * DIM
                                                    : t + (size_t)(gj - N_ROWS) * DIM;
                    float a2 = 0.f;
                    for (int k = 0; k < DIM; k += 4) {
                        float4 a = *(const float4*)(pi + k);
                        float4 b = *(const float4*)(pj + k);
                        float e0 = a.x - b.x, e1 = a.y - b.y, e2 = a.z - b.z, e3 = a.w - b.w;
                        a2 += e0 * e0 + e1 * e1 + e2 * e2 + e3 * e3;
                    }
                    local += wgt * expf(-0.5f * a2);
                }
            }
        }
    }
    local *= sgn;
#pragma unroll
    for (int o = 16; o; o >>= 1) local += __shfl_xor_sync(0xffffffffu, local, o);
    if (!lane) rsum[wid] = local;
    __syncthreads();
    if (tid == 0) {
        float tot = 0.f;
#pragma unroll
        for (int i = 0; i < 8; i++) tot += rsum[i];
        if (tot != 0.f) atomicAdd(&g_acc[0], tot);
    }
}

// ================= final combine =================
__global__ void k_final(float* __restrict__ out) {
    float mmd = (g_acc[0] + (float)TWO_N) / ((float)N_ROWS * (float)N_ROWS);
    float adv = -g_acc[1] / (float)N_ROWS - g_acc[2] / (float)N_ROWS;
    float w = g_acc[3];
    out[0] = w * mmd + (1.f - w) * adv;
}

// ================= launch (single stream) =================
extern "C" void kernel_launch(void* const* d_in, const int* in_sizes, int n_in,
                              void* d_out, int out_size) {
    const float* s   = (const float*)d_in[0];
    const float* t   = (const float*)d_in[1];
    const float* dW1 = (const float*)d_in[2];
    const float* db1 = (const float*)d_in[3];
    const float* dW2 = (const float*)d_in[4];
    const float* db2 = (const float*)d_in[5];
    const float* dW3 = (const float*)d_in[6];
    const float* db3 = (const float*)d_in[7];
    const float* wW1 = (const float*)d_in[8];
    const float* wb1 = (const float*)d_in[9];
    const float* wW2 = (const float*)d_in[10];
    const float* wb2 = (const float*)d_in[11];
    const float* wW3 = (const float*)d_in[12];
    const float* wb3 = (const float*)d_in[13];
    float* out = (float*)d_out;

    cudaFuncSetAttribute(k_disc_mma, cudaFuncAttributeMaxDynamicSharedMemorySize, DISC_SMEM);
    cudaFuncSetAttribute(k_mmd_hmma, cudaFuncAttributeMaxDynamicSharedMemorySize, MMD_SMEM);

    k_init<<<512, 256>>>(dW1, dW2);
    k_prep<<<TWO_N / 32, 256>>>(s, t);
    k_stats<<<1, 512>>>(wW1, wb1, wW2, wb2, wW3, wb3, out);
    k_disc_mma<<<256, 256, DISC_SMEM>>>(db1, db2, dW3, db3);
    k_mmd_hmma<<<NTRI, 256, MMD_SMEM>>>(s, t);
    k_final<<<1, 1>>>(out);
}

// round 16
// speedup vs baseline: 1.1102x; 1.0070x over previous
#include <cuda_runtime.h>
#include <cuda_bf16.h>
#include <math.h>
#include <stdint.h>

#define N_ROWS 8192
#define DIM    512
#define KSUB   160          // screening subspace (first 160 dims)
#define TWO_N  16384

// ================= device scratch =================
__device__ float g_mean[2][DIM];
__device__ float g_energy[2][DIM];
__device__ float g_var[2][DIM];
__device__ float g_kurt[2][DIM];
__device__ float g_skew[2][DIM];
__device__ float g_rnsub[TWO_N];             // squared norm over first KSUB dims
__device__ float g_cacc[2][4][DIM];          // raw moment partials S1..S4
__device__ float g_acc[4];                   // 0 mmd-sum, 1 log(p) src, 2 log(1-p) tgt, 3 weight
__device__ __nv_bfloat16 g_ubf[(size_t)TWO_N * DIM];   // bf16 copy of u=[s;t], full 512 dims
__device__ __nv_bfloat16 g_w1t[256 * 512];   // W1^T bf16 [n][k]
__device__ __nv_bfloat16 g_w2t[128 * 256];   // W2^T bf16 [n][k]

// ================= helpers =================
__device__ __forceinline__ void cp16(uint32_t dst_smem, const void* src) {
    asm volatile("cp.async.cg.shared.global [%0], [%1], 16;" :: "r"(dst_smem), "l"(src));
}
__device__ __forceinline__ void mma16816(float* c, const uint32_t* a, const uint32_t* b) {
    asm volatile(
        "mma.sync.aligned.m16n8k16.row.col.f32.bf16.bf16.f32 "
        "{%0,%1,%2,%3}, {%4,%5,%6,%7}, {%8,%9}, {%0,%1,%2,%3};"
        : "+f"(c[0]), "+f"(c[1]), "+f"(c[2]), "+f"(c[3])
        : "r"(a[0]), "r"(a[1]), "r"(a[2]), "r"(a[3]), "r"(b[0]), "r"(b[1]));
}
__device__ __forceinline__ void ldm_x4(uint32_t* r, uint32_t addr) {
    asm volatile("ldmatrix.sync.aligned.m8n8.x4.shared.b16 {%0,%1,%2,%3}, [%4];"
        : "=r"(r[0]), "=r"(r[1]), "=r"(r[2]), "=r"(r[3]) : "r"(addr));
}

// ================= init: zero accumulators + weight transpose/convert =================
__global__ void k_init(const float* __restrict__ W1, const float* __restrict__ W2) {
    int i = blockIdx.x * 256 + threadIdx.x;
    if (i < 2 * 4 * DIM) (&g_cacc[0][0][0])[i] = 0.f;
    if (i < 4) g_acc[i] = 0.f;
    if (i < 256 * 512) { int n = i >> 9, k = i & 511; g_w1t[i] = __float2bfloat16(W1[k * 256 + n]); }
    if (i < 128 * 256) { int n = i >> 8, k = i & 255; g_w2t[i] = __float2bfloat16(W2[k * 128 + n]); }
}

// ================= fused prep: bf16 convert + rnsub + raw column moments =================
// grid 512, 256 threads, 32 rows of u per block
__global__ void __launch_bounds__(256) k_prep(const float* __restrict__ s,
                                              const float* __restrict__ t) {
    __shared__ float sh_rn[32];
    int tid = threadIdx.x, lane = tid & 31, wid = tid >> 5;
    if (tid < 32) sh_rn[tid] = 0.f;
    __syncthreads();

    int row0 = blockIdx.x * 32;
    int tensor = (row0 >= N_ROWS);
    const float* X = tensor ? t + (size_t)(row0 - N_ROWS) * DIM : s + (size_t)row0 * DIM;
    int c4 = tid & 127;
    int rg = tid >> 7;
    bool inc = (c4 < KSUB / 4);
    bool subw = ((wid & 3) < 2);

    float M1[4] = {0.f, 0.f, 0.f, 0.f}, M2[4] = {0.f, 0.f, 0.f, 0.f};
    float M3[4] = {0.f, 0.f, 0.f, 0.f}, M4[4] = {0.f, 0.f, 0.f, 0.f};

#pragma unroll 4
    for (int i = 0; i < 16; i++) {
        int r = rg * 16 + i;
        float4 v = ((const float4*)(X + (size_t)r * DIM))[c4];
        __nv_bfloat162* dst = (__nv_bfloat162*)(g_ubf + (size_t)(row0 + r) * DIM);
        dst[c4 * 2]     = __floats2bfloat162_rn(v.x, v.y);
        dst[c4 * 2 + 1] = __floats2bfloat162_rn(v.z, v.w);
        float vv[4] = {v.x, v.y, v.z, v.w};
        float rn = 0.f;
#pragma unroll
        for (int j = 0; j < 4; j++) {
            float x = vv[j], x2 = x * x;
            M1[j] += x; M2[j] += x2; M3[j] += x2 * x; M4[j] += x2 * x2;
            rn += x2;
        }
        if (subw) {
            rn = inc ? rn : 0.f;
#pragma unroll
            for (int o = 16; o; o >>= 1) rn += __shfl_xor_sync(0xffffffffu, rn, o);
            if (!lane) atomicAdd(&sh_rn[r], rn);
        }
    }
    __syncthreads();
    if (tid < 32) g_rnsub[row0 + tid] = sh_rn[tid];

#pragma unroll
    for (int j = 0; j < 4; j++) {
        int c = c4 * 4 + j;
        atomicAdd(&g_cacc[tensor][0][c], M1[j]);
        atomicAdd(&g_cacc[tensor][1][c], M2[j]);
        atomicAdd(&g_cacc[tensor][2][c], M3[j]);
        atomicAdd(&g_cacc[tensor][3][c], M4[j]);
    }
}

// ================= fused: central moments + stat-diff MLP (1 block, 512 thr) =================
__global__ void k_stats(const float* __restrict__ wW1, const float* __restrict__ wb1,
                        const float* __restrict__ wW2, const float* __restrict__ wb2,
                        const float* __restrict__ wW3, const float* __restrict__ wb3,
                        float* __restrict__ out) {
    int tid = threadIdx.x;
    const float n = (float)N_ROWS;

    for (int i = tid; i < 2 * DIM; i += 512) {
        int tensor = i >> 9, c = i & 511;
        float S1 = g_cacc[tensor][0][c], S2 = g_cacc[tensor][1][c];
        float S3 = g_cacc[tensor][2][c], S4 = g_cacc[tensor][3][c];
        float m = S1 / n;
        float c2 = S2 - m * S1;
        float c3 = S3 - 3.f * m * S2 + 2.f * m * m * S1;
        float c4 = S4 - 4.f * m * S3 + 6.f * m * m * S2 - 3.f * m * m * m * S1;
        float var = c2 / (n - 1.f);
        float inv = 1.f / (sqrtf(var) + 1e-8f);
        float inv3 = inv * inv * inv;
        g_mean[tensor][c]   = m;
        g_energy[tensor][c] = S2 / n;
        g_var[tensor][c]    = var;
        g_skew[tensor][c]   = c3 * inv3 / n;
        g_kurt[tensor][c]   = c4 * inv3 * inv / n - 3.f;
    }
    __syncthreads();

    __shared__ float red[5][512];
    float l[5] = {0.f, 0.f, 0.f, 0.f, 0.f};
    if (tid < DIM) {
        l[0] = fabsf(g_mean[0][tid]   - g_mean[1][tid]);
        l[1] = fabsf(g_var[0][tid]    - g_var[1][tid]);
        l[2] = fabsf(g_kurt[0][tid]   - g_kurt[1][tid]);
        l[3] = fabsf(g_skew[0][tid]   - g_skew[1][tid]);
        l[4] = fabsf(g_energy[0][tid] - g_energy[1][tid]);
    }
#pragma unroll
    for (int k = 0; k < 5; k++) red[k][tid] = l[k];
    __syncthreads();
    for (int stride = 256; stride > 0; stride >>= 1) {
        if (tid < stride)
#pragma unroll
            for (int k = 0; k < 5; k++) red[k][tid] += red[k][tid + stride];
        __syncthreads();
    }
    __shared__ float diff[6], h1[32], h2[16];
    if (tid < 6) diff[tid] = (tid < 5) ? red[tid][0] / (float)DIM : 0.f;
    __syncthreads();
    if (tid < 32) {
        float a = wb1[tid];
#pragma unroll
        for (int k = 0; k < 6; k++) a += diff[k] * wW1[k * 32 + tid];
        h1[tid] = fmaxf(a, 0.f);
    }
    __syncthreads();
    if (tid < 16) {
        float a = wb2[tid];
#pragma unroll
        for (int k = 0; k < 32; k++) a += h1[k] * wW2[k * 16 + tid];
        h2[tid] = fmaxf(a, 0.f);
    }
    __syncthreads();
    if (tid == 0) {
        float z = wb3[0];
#pragma unroll
        for (int k = 0; k < 16; k++) z += h2[k] * wW3[k];
        float wgt = 1.f / (1.f + expf(-z));
        g_acc[3] = wgt;
        out[1] = wgt;
    }
}

// ================= discriminator MLP + BCE via HMMA =================
// layer 1: 3-buffer 1-sync pipeline; layer 2: all 8 warps (16 N-cols each)
#define DST 40
#define H1ST 264
#define ASTAGE (64 * DST * 2)            // 5120
#define BSTAGE (256 * DST * 2)           // 20480
#define SM_A 0                           // 3 x ASTAGE = 15360
#define SM_B 15360                       // 3 x BSTAGE = 61440 -> ends 76800
#define SM_H1 76800                      // 64 x H1ST x 2 = 33792 -> ends 110592
#define SM_ZP 110592                     // 64 x 4
#define SM_B1 110848                     // 256 x 4
#define SM_B2 111872                     // 128 x 4
#define SM_W3 112384                     // 128 x 4
#define DISC_SMEM 112896

__global__ void __launch_bounds__(256, 2) k_disc_mma(
    const float* __restrict__ b1, const float* __restrict__ b2,
    const float* __restrict__ W3, const float* __restrict__ b3) {
    extern __shared__ char smc[];
    uint32_t sm = (uint32_t)__cvta_generic_to_shared(smc);
    float* b1s = (float*)(smc + SM_B1);
    float* b2s = (float*)(smc + SM_B2);
    float* w3s = (float*)(smc + SM_W3);
    float* zps = (float*)(smc + SM_ZP);
    __nv_bfloat16* h1s = (__nv_bfloat16*)(smc + SM_H1);

    int tid = threadIdx.x, lane = tid & 31, wid = tid >> 5;
    int gid = lane >> 2, tig = lane & 3;
    int blk = blockIdx.x;
    bool srcblk = blk < 128;
    int row0 = blk * 64;

    if (tid < 256) b1s[tid] = b1[tid];
    if (tid < 128) { b2s[tid] = b2[tid]; w3s[tid] = W3[tid]; }
    if (tid < 64) zps[tid] = 0.f;

    uint32_t a_lo = (uint32_t)((lane & 15) * (DST * 2) + (lane >> 4) * 16);
    uint32_t b_lo = (uint32_t)(((lane & 7) + ((lane >> 4) * 8)) * (DST * 2) + ((lane >> 3) & 1) * 16);

    const __nv_bfloat16* gA = g_ubf + (size_t)row0 * DIM;

    // ---- layer 1: X[64,512] @ W1t^T -> h1[64,256], 3-buffer 1-sync ----
    auto issue1 = [&](int kt, int buf) {
#pragma unroll
        for (int q = 0; q < 5; q++) {
            int c = tid + q * 256;
            if (c < 256) {
                int row = c >> 2, cg = c & 3;
                cp16(sm + SM_A + buf * ASTAGE + row * (DST * 2) + cg * 16,
                     gA + (size_t)row * DIM + kt * 32 + cg * 8);
            } else {
                int b = c - 256;
                int row = b >> 2, cg = b & 3;
                cp16(sm + SM_B + buf * BSTAGE + row * (DST * 2) + cg * 16,
                     g_w1t + (size_t)row * 512 + kt * 32 + cg * 8);
            }
        }
        asm volatile("cp.async.commit_group;" ::: "memory");
    };

    float acc[4][4][4];
#pragma unroll
    for (int i = 0; i < 4; i++)
#pragma unroll
        for (int j = 0; j < 4; j++)
#pragma unroll
            for (int e = 0; e < 4; e++) acc[i][j][e] = 0.f;

    issue1(0, 0);
    issue1(1, 1);
    for (int kt = 0; kt < 16; kt++) {
        int buf = kt % 3;
        if (kt < 15) asm volatile("cp.async.wait_group 1;" ::: "memory");
        else         asm volatile("cp.async.wait_group 0;" ::: "memory");
        __syncthreads();                     // single barrier per stage
        if (kt + 2 < 16) issue1(kt + 2, (kt + 2) % 3);

        uint32_t aS = sm + SM_A + buf * ASTAGE + a_lo;
        uint32_t bS = sm + SM_B + buf * BSTAGE + (uint32_t)(wid * 32) * (DST * 2) + b_lo;
#pragma unroll
        for (int ks = 0; ks < 2; ks++) {
            uint32_t kb2 = ks * 32;
            uint32_t af[4][4], bf[4][2];
#pragma unroll
            for (int mt = 0; mt < 4; mt++)
                ldm_x4(af[mt], aS + (uint32_t)(mt * 16) * (DST * 2) + kb2);
#pragma unroll
            for (int p = 0; p < 2; p++) {
                uint32_t bq[4];
                ldm_x4(bq, bS + (uint32_t)(p * 16) * (DST * 2) + kb2);
                bf[2 * p][0] = bq[0]; bf[2 * p][1] = bq[1];
                bf[2 * p + 1][0] = bq[2]; bf[2 * p + 1][1] = bq[3];
            }
#pragma unroll
            for (int mt = 0; mt < 4; mt++)
#pragma unroll
                for (int nt = 0; nt < 4; nt++)
                    mma16816(acc[mt][nt], af[mt], bf[nt]);
        }
    }
    __syncthreads();

    // epilogue 1: relu + bias -> h1 (bf16, padded stride)
#pragma unroll
    for (int mt = 0; mt < 4; mt++) {
#pragma unroll
        for (int nt = 0; nt < 4; nt++) {
            int col0 = wid * 32 + nt * 8 + 2 * tig;
#pragma unroll
            for (int e = 0; e < 4; e++) {
                int row = mt * 16 + gid + ((e >= 2) ? 8 : 0);
                int col = col0 + (e & 1);
                float v = fmaxf(acc[mt][nt][e] + b1s[col], 0.f);
                h1s[row * H1ST + col] = __float2bfloat16(v);
            }
        }
    }
    __syncthreads();

    // ---- layer 2: h1[64,256] @ W2t^T -> h2[64,128], all 8 warps, 16 N each ----
    auto issue2 = [&](int kt, int st) {
#pragma unroll
        for (int q = 0; q < 2; q++) {
            int c = tid + q * 256;
            int row = c >> 2, cg = c & 3;
            cp16(sm + SM_B + st * BSTAGE + row * (DST * 2) + cg * 16,
                 g_w2t + (size_t)row * 256 + kt * 32 + cg * 8);
        }
        asm volatile("cp.async.commit_group;" ::: "memory");
    };

#pragma unroll
    for (int i = 0; i < 4; i++)
#pragma unroll
        for (int j = 0; j < 2; j++)
#pragma unroll
            for (int e = 0; e < 4; e++) acc[i][j][e] = 0.f;

    uint32_t a_lo2 = (uint32_t)((lane & 15) * (H1ST * 2) + (lane >> 4) * 16);
    issue2(0, 0);
    for (int kt = 0; kt < 8; kt++) {
        int st = kt & 1;
        if (kt < 7) { issue2(kt + 1, st ^ 1); asm volatile("cp.async.wait_group 1;" ::: "memory"); }
        else        { asm volatile("cp.async.wait_group 0;" ::: "memory"); }
        __syncthreads();
        {
            uint32_t aS = sm + SM_H1 + a_lo2 + (uint32_t)(kt * 64);
            uint32_t bS = sm + SM_B + st * BSTAGE + (uint32_t)(wid * 16) * (DST * 2) + b_lo;
#pragma unroll
            for (int ks = 0; ks < 2; ks++) {
                uint32_t kb2 = ks * 32;
                uint32_t af[4][4], bf[2][2];
#pragma unroll
                for (int mt = 0; mt < 4; mt++)
                    ldm_x4(af[mt], aS + (uint32_t)(mt * 16) * (H1ST * 2) + kb2);
                {
                    uint32_t bq[4];
                    ldm_x4(bq, bS + kb2);
                    bf[0][0] = bq[0]; bf[0][1] = bq[1];
                    bf[1][0] = bq[2]; bf[1][1] = bq[3];
                }
#pragma unroll
                for (int mt = 0; mt < 4; mt++)
#pragma unroll
                    for (int nt = 0; nt < 2; nt++)
                        mma16816(acc[mt][nt], af[mt], bf[nt]);
            }
        }
        __syncthreads();
    }

    // epilogue 2: zp[row] += relu(h2 + b2) * W3  (all 8 warps, 16 cols each)
    {
#pragma unroll
        for (int mt = 0; mt < 4; mt++) {
            float zp0 = 0.f, zp1 = 0.f;
#pragma unroll
            for (int nt = 0; nt < 2; nt++) {
                int col0 = wid * 16 + nt * 8 + 2 * tig;
                float w30 = w3s[col0], w31 = w3s[col0 + 1];
                float bb0 = b2s[col0], bb1 = b2s[col0 + 1];
                zp0 += fmaxf(acc[mt][nt][0] + bb0, 0.f) * w30
                     + fmaxf(acc[mt][nt][1] + bb1, 0.f) * w31;
                zp1 += fmaxf(acc[mt][nt][2] + bb0, 0.f) * w30
                     + fmaxf(acc[mt][nt][3] + bb1, 0.f) * w31;
            }
            atomicAdd(&zps[mt * 16 + gid], zp0);
            atomicAdd(&zps[mt * 16 + gid + 8], zp1);
        }
    }
    __syncthreads();

    if (tid < 64) {
        float z = zps[tid] + b3[0];
        float p = 1.f / (1.f + expf(-z));
        float term = srcblk ? fmaxf(logf(p), -100.f) : fmaxf(logf(1.f - p), -100.f);
#pragma unroll
        for (int o = 16; o; o >>= 1) term += __shfl_xor_sync(0xffffffffu, term, o);
        if (!lane) zps[wid] = term;
    }
    __syncthreads();
    if (tid == 0) atomicAdd(&g_acc[srcblk ? 1 : 2], zps[0] + zps[1]);
}

// ================= MMD: K=160 screening Gram, 3-buffer 1-sync pipeline =================
#define AST 40                           // smem row stride (bf16): 80 B, conflict-free
#define STG (128 * AST * 2)              // 10240 B per stage per matrix
#define OFF_B  (3 * STG)                 // 30720
#define OFF_RNI (6 * STG)                // 61440
#define OFF_RNJ (OFF_RNI + 512)
#define OFF_RS  (OFF_RNJ + 512)
#define MMD_SMEM (OFF_RS + 32)           // 62496
#define NTILE 128
#define NTRI  (NTILE * (NTILE + 1) / 2)  // 8256
#define NSTAGE (KSUB / 32)               // 5

__global__ void __launch_bounds__(256, 2) k_mmd_hmma(const float* __restrict__ s,
                                                     const float* __restrict__ t) {
    int idx = blockIdx.x;
    int by = (int)(128.5f - sqrtf(128.5f * 128.5f - 2.0f * (float)idx));
    while ((by + 1) * NTILE - ((by + 1) * by) / 2 <= idx) by++;
    while (by * NTILE - (by * (by - 1)) / 2 > idx) by--;
    int bx = by + (idx - (by * NTILE - (by * (by - 1)) / 2));

    extern __shared__ char smc[];
    uint32_t sm = (uint32_t)__cvta_generic_to_shared(smc);
    float* rni_s = (float*)(smc + OFF_RNI);
    float* rnj_s = (float*)(smc + OFF_RNJ);
    float* rsum  = (float*)(smc + OFF_RS);

    int tid = threadIdx.x, lane = tid & 31, wid = tid >> 5;
    int wm = wid & 1, wn = wid >> 1;
    int gid = lane >> 2, tig = lane & 3;
    int arow0 = by * 128, brow0 = bx * 128;

    if (tid < 128) {
        rni_s[tid] = g_rnsub[arow0 + tid];
        rnj_s[tid] = g_rnsub[brow0 + tid];
    }

    const __nv_bfloat16* gA = g_ubf + (size_t)arow0 * DIM;
    const __nv_bfloat16* gB = g_ubf + (size_t)brow0 * DIM;

    uint32_t a_lo = (uint32_t)((lane & 15) * (AST * 2) + (lane >> 4) * 16);
    uint32_t b_lo = (uint32_t)(((lane & 7) + ((lane >> 4) * 8)) * (AST * 2) + ((lane >> 3) & 1) * 16);

    float acc[4][4][4];
#pragma unroll
    for (int i = 0; i < 4; i++)
#pragma unroll
        for (int j = 0; j < 4; j++)
#pragma unroll
            for (int e = 0; e < 4; e++) acc[i][j][e] = 0.f;

    auto issue = [&](int kt, int buf) {
#pragma unroll
        for (int q = 0; q < 2; q++) {
            int c = tid + q * 256;
            int row = c >> 2, cg = c & 3;
            size_t goff = (size_t)row * DIM + (size_t)kt * 32 + cg * 8;
            uint32_t soff = (uint32_t)(buf * STG + row * (AST * 2) + cg * 16);
            cp16(sm + soff, gA + goff);
            cp16(sm + OFF_B + soff, gB + goff);
        }
        asm volatile("cp.async.commit_group;" ::: "memory");
    };

    issue(0, 0);
    issue(1, 1);
#pragma unroll
    for (int kt = 0; kt < NSTAGE; kt++) {
        int buf = kt % 3;
        if (kt < NSTAGE - 1) asm volatile("cp.async.wait_group 1;" ::: "memory");
        else                 asm volatile("cp.async.wait_group 0;" ::: "memory");
        __syncthreads();
        if (kt + 2 < NSTAGE) issue(kt + 2, (kt + 2) % 3);

        uint32_t aS = sm + buf * STG + (uint32_t)(wm * 64) * (AST * 2) + a_lo;
        uint32_t bS = sm + OFF_B + buf * STG + (uint32_t)(wn * 32) * (AST * 2) + b_lo;
#pragma unroll
        for (int ks = 0; ks < 2; ks++) {
            uint32_t kb2 = ks * 32;
            uint32_t af[4][4], bf[4][2];
#pragma unroll
            for (int mt = 0; mt < 4; mt++)
                ldm_x4(af[mt], aS + (uint32_t)(mt * 16) * (AST * 2) + kb2);
#pragma unroll
            for (int p = 0; p < 2; p++) {
                uint32_t bq[4];
                ldm_x4(bq, bS + (uint32_t)(p * 16) * (AST * 2) + kb2);
                bf[2 * p][0] = bq[0]; bf[2 * p][1] = bq[1];
                bf[2 * p + 1][0] = bq[2]; bf[2 * p + 1][1] = bq[3];
            }
#pragma unroll
            for (int mt = 0; mt < 4; mt++)
#pragma unroll
                for (int nt = 0; nt < 4; nt++)
                    mma16816(acc[mt][nt], af[mt], bf[nt]);
        }
    }

    bool diag = (bx == by);
    float sgn = ((by < 64) == (bx < 64)) ? 1.f : -1.f;
    float local = 0.f;

#pragma unroll
    for (int mt = 0; mt < 4; mt++) {
        int li0 = wm * 64 + mt * 16 + gid;
        float rn0 = rni_s[li0], rn1 = rni_s[li0 + 8];
#pragma unroll
        for (int nt = 0; nt < 4; nt++) {
            int lj0 = wn * 32 + nt * 8 + 2 * tig;
#pragma unroll
            for (int e = 0; e < 4; e++) {
                int li = li0 + ((e >= 2) ? 8 : 0);
                int lj = lj0 + (e & 1);
                float rn_i = (e >= 2) ? rn1 : rn0;
                float rj = rnj_s[lj];
                float d2s = rn_i + rj - 2.f * acc[mt][nt][e];
                int gi = arow0 + li, gj = brow0 + lj;
                float wgt = diag ? ((gj > gi) ? 2.f : 0.f) : 2.f;
                if (wgt != 0.f && d2s < 164.f + 0.01f * (rn_i + rj)) {
                    const float* pi = (gi < N_ROWS) ? s + (size_t)gi * DIM
                                                    : t + (size_t)(gi - N_ROWS) * DIM;
                    const float* pj = (gj < N_ROWS) ? s + (size_t)gj * DIM
                                                    : t + (size_t)(gj - N_ROWS) * DIM;
                    float a2 = 0.f;
                    for (int k = 0; k < DIM; k += 4) {
                        float4 a = *(const float4*)(pi + k);
                        float4 b = *(const float4*)(pj + k);
                        float e0 = a.x - b.x, e1 = a.y - b.y, e2 = a.z - b.z, e3 = a.w - b.w;
                        a2 += e0 * e0 + e1 * e1 + e2 * e2 + e3 * e3;
                    }
                    local += wgt * expf(-0.5f * a2);
                }
            }
        }
    }
    local *= sgn;
#pragma unroll
    for (int o = 16; o; o >>= 1) local += __shfl_xor_sync(0xffffffffu, local, o);
    if (!lane) rsum[wid] = local;
    __syncthreads();
    if (tid == 0) {
        float tot = 0.f;
#pragma unroll
        for (int i = 0; i < 8; i++) tot += rsum[i];
        if (tot != 0.f) atomicAdd(&g_acc[0], tot);
    }
}

// ================= final combine =================
__global__ void k_final(float* __restrict__ out) {
    float mmd = (g_acc[0] + (float)TWO_N) / ((float)N_ROWS * (float)N_ROWS);
    float adv = -g_acc[1] / (float)N_ROWS - g_acc[2] / (float)N_ROWS;
    float w = g_acc[3];
    out[0] = w * mmd + (1.f - w) * adv;
}

// ================= launch (single stream) =================
extern "C" void kernel_launch(void* const* d_in, const int* in_sizes, int n_in,
                              void* d_out, int out_size) {
    const float* s   = (const float*)d_in[0];
    const float* t   = (const float*)d_in[1];
    const float* dW1 = (const float*)d_in[2];
    const float* db1 = (const float*)d_in[3];
    const float* dW2 = (const float*)d_in[4];
    const float* db2 = (const float*)d_in[5];
    const float* dW3 = (const float*)d_in[6];
    const float* db3 = (const float*)d_in[7];
    const float* wW1 = (const float*)d_in[8];
    const float* wb1 = (const float*)d_in[9];
    const float* wW2 = (const float*)d_in[10];
    const float* wb2 = (const float*)d_in[11];
    const float* wW3 = (const float*)d_in[12];
    const float* wb3 = (const float*)d_in[13];
    float* out = (float*)d_out;

    cudaFuncSetAttribute(k_disc_mma, cudaFuncAttributeMaxDynamicSharedMemorySize, DISC_SMEM);
    cudaFuncSetAttribute(k_mmd_hmma, cudaFuncAttributeMaxDynamicSharedMemorySize, MMD_SMEM);

    k_init<<<512, 256>>>(dW1, dW2);
    k_prep<<<TWO_N / 32, 256>>>(s, t);
    k_stats<<<1, 512>>>(wW1, wb1, wW2, wb2, wW3, wb3, out);
    k_disc_mma<<<256, 256, DISC_SMEM>>>(db1, db2, dW3, db3);
    k_mmd_hmma<<<NTRI, 256, MMD_SMEM>>>(s, t);
    k_final<<<1, 1>>>(out);
}